// round 12
// baseline (speedup 1.0000x reference)
#include <cuda_runtime.h>
#include <cuda_bf16.h>
#include <cstdint>

#define BB 32
#define TT 64
#define SS 128
#define EE 256
#define HH 512
#define ENCC 512
#define VV 32000
#define NDEC 32   // blocks in persistent decode kernel (one wave, co-resident)

// ---------------- scratch (device globals; no allocation) ----------------
__device__ float g_gatesx[BB * TT * 4 * HH];        // 16 MB [b,t,4H] = emb@Wih^T + bias
__device__ float g_hhist[BB * TT * HH];             // 4 MB  h after step t: [b,t,h]
__device__ float g_proj_enc[BB * SS * HH];          // 8 MB  enc @ Wa^T
__device__ float g_proj2[BB * SS * HH];             // 8 MB  enc @ Wc_c^T
__device__ float g_att2[BB * TT * SS];              // 1 MB  att per (b,t)
__device__ float g_ho[BB * TT * HH];                // 4 MB
__device__ float g_bias2[4 * HH];                   // b_ih + b_hh
__device__ unsigned g_bar[TT];                      // decode grid barrier counters
// tf32 hi/lo planes (precomputed once per launch):
__device__ uint32_t g_whh_hi[4 * HH * HH];          // 4 MB, rearranged [blk][z][jj][k]
__device__ uint32_t g_whh_lo[4 * HH * HH];          // 4 MB
__device__ uint32_t g_hpl[2][2][BB * HH];           // [parity][hi/lo][b*H+j]

// ---------------- helpers ----------------
__device__ __forceinline__ uint32_t f2tf32(float x) {
    uint32_t r;
    asm("cvt.rna.tf32.f32 %0, %1;" : "=r"(r) : "f"(x));
    return r;
}

__device__ __forceinline__ void mma_tf32(float* d, const uint32_t* a, const uint32_t* b) {
    asm("mma.sync.aligned.m16n8k8.row.col.f32.tf32.tf32.f32 "
        "{%0,%1,%2,%3}, {%4,%5,%6,%7}, {%8,%9}, {%0,%1,%2,%3};"
        : "+f"(d[0]), "+f"(d[1]), "+f"(d[2]), "+f"(d[3])
        : "r"(a[0]), "r"(a[1]), "r"(a[2]), "r"(a[3]), "r"(b[0]), "r"(b[1]));
}

__device__ __forceinline__ float sigf(float x) { return 1.0f / (1.0f + expf(-x)); }

// ------- double-buffered tf32 GEMM: C[M,N] = A[M,K] @ B[N,K]^T (+bias) -----------
template <bool COMP, bool GATHER>
__global__ __launch_bounds__(256) void gemm_db(
    const float* __restrict__ A, int lda, const int* __restrict__ gidx,
    const float* __restrict__ B, int ldb,
    float* __restrict__ C, int ldc,
    const float* __restrict__ bias0, int K)
{
    constexpr int KT = COMP ? 16 : 32;
    constexpr int PAD = COMP ? 20 : 36;
    constexpr int PLANE = 128 * PAD;
    constexpr int NPL = COMP ? 2 : 1;
    constexpr int STG = NPL * PLANE;
    constexpr int C4 = KT / 4;
    constexpr int NL = (128 * C4) / 256;

    extern __shared__ uint32_t sm[];
    uint32_t* As = sm;
    uint32_t* Bs = sm + 2 * STG;

    const int tid = threadIdx.x;
    const int warp = tid >> 5, lane = tid & 31;
    const int g = lane >> 2, tg = lane & 3;
    const int wm = (warp & 1) * 64, wn = (warp >> 1) * 32;
    const long m0 = (long)blockIdx.y * 128, n0 = (long)blockIdx.x * 128;

    float acc[4][4][4];
#pragma unroll
    for (int i = 0; i < 4; i++)
#pragma unroll
        for (int j = 0; j < 4; j++)
#pragma unroll
            for (int q = 0; q < 4; q++) acc[i][j][q] = 0.0f;

    const int nk = K / KT;
    float4 ra[NL], rb[NL];

    auto ldg_tile = [&](int kt) {
#pragma unroll
        for (int i = 0; i < NL; i++) {
            int idx = i * 256 + tid;
            int row = idx / C4, c4 = idx % C4;
            const float* ap = GATHER ? (A + (size_t)gidx[m0 + row] * lda)
                                     : (A + (size_t)(m0 + row) * lda);
            ra[i] = *(const float4*)(ap + kt + c4 * 4);
            rb[i] = *(const float4*)(B + (size_t)(n0 + row) * ldb + kt + c4 * 4);
        }
    };
    auto sts_tile = [&](int stg) {
        uint32_t* as = As + stg * STG;
        uint32_t* bs = Bs + stg * STG;
#pragma unroll
        for (int i = 0; i < NL; i++) {
            int idx = i * 256 + tid;
            int row = idx / C4, c4 = idx % C4;
            uint32_t* da = &as[row * PAD + c4 * 4];
            uint32_t* db = &bs[row * PAD + c4 * 4];
            float av[4] = {ra[i].x, ra[i].y, ra[i].z, ra[i].w};
            float bv[4] = {rb[i].x, rb[i].y, rb[i].z, rb[i].w};
#pragma unroll
            for (int q = 0; q < 4; q++) {
                uint32_t ah = f2tf32(av[q]);
                uint32_t bh = f2tf32(bv[q]);
                da[q] = ah;
                db[q] = bh;
                if (COMP) {
                    da[q + PLANE] = f2tf32(av[q] - __uint_as_float(ah));
                    db[q + PLANE] = f2tf32(bv[q] - __uint_as_float(bh));
                }
            }
        }
    };

    ldg_tile(0);
    sts_tile(0);
    __syncthreads();

    for (int ki = 0; ki < nk; ki++) {
        const int cur = ki & 1;
        if (ki + 1 < nk) ldg_tile((ki + 1) * KT);

        const uint32_t* Ac = As + cur * STG;
        const uint32_t* Bc = Bs + cur * STG;
#pragma unroll
        for (int ks = 0; ks < KT / 8; ks++) {
            const int k0 = ks * 8;
            uint32_t ah[4][4], bh[4][2];
#pragma unroll
            for (int mt = 0; mt < 4; mt++) {
                int rb2 = wm + mt * 16;
                ah[mt][0] = Ac[(rb2 + g) * PAD + k0 + tg];
                ah[mt][1] = Ac[(rb2 + g + 8) * PAD + k0 + tg];
                ah[mt][2] = Ac[(rb2 + g) * PAD + k0 + tg + 4];
                ah[mt][3] = Ac[(rb2 + g + 8) * PAD + k0 + tg + 4];
            }
#pragma unroll
            for (int nt = 0; nt < 4; nt++) {
                int nb = wn + nt * 8 + g;
                bh[nt][0] = Bc[nb * PAD + k0 + tg];
                bh[nt][1] = Bc[nb * PAD + k0 + tg + 4];
            }
            if (COMP) {
                uint32_t al[4][4], bl[4][2];
#pragma unroll
                for (int mt = 0; mt < 4; mt++) {
                    int rb2 = wm + mt * 16;
                    al[mt][0] = Ac[PLANE + (rb2 + g) * PAD + k0 + tg];
                    al[mt][1] = Ac[PLANE + (rb2 + g + 8) * PAD + k0 + tg];
                    al[mt][2] = Ac[PLANE + (rb2 + g) * PAD + k0 + tg + 4];
                    al[mt][3] = Ac[PLANE + (rb2 + g + 8) * PAD + k0 + tg + 4];
                }
#pragma unroll
                for (int nt = 0; nt < 4; nt++) {
                    int nb = wn + nt * 8 + g;
                    bl[nt][0] = Bc[PLANE + nb * PAD + k0 + tg];
                    bl[nt][1] = Bc[PLANE + nb * PAD + k0 + tg + 4];
                }
#pragma unroll
                for (int mt = 0; mt < 4; mt++)
#pragma unroll
                    for (int nt = 0; nt < 4; nt++) {
                        mma_tf32(acc[mt][nt], ah[mt], bh[nt]);
                        mma_tf32(acc[mt][nt], al[mt], bh[nt]);
                        mma_tf32(acc[mt][nt], ah[mt], bl[nt]);
                    }
            } else {
#pragma unroll
                for (int mt = 0; mt < 4; mt++)
#pragma unroll
                    for (int nt = 0; nt < 4; nt++)
                        mma_tf32(acc[mt][nt], ah[mt], bh[nt]);
            }
        }

        if (ki + 1 < nk) sts_tile(1 - cur);
        __syncthreads();
    }

#pragma unroll
    for (int nt = 0; nt < 4; nt++) {
        long col = n0 + wn + nt * 8 + 2 * tg;
        float bv0 = bias0 ? bias0[col] : 0.0f;
        float bv1 = bias0 ? bias0[col + 1] : 0.0f;
#pragma unroll
        for (int mt = 0; mt < 4; mt++) {
            long row = m0 + wm + mt * 16 + g;
            float2 r0 = make_float2(acc[mt][nt][0] + bv0, acc[mt][nt][1] + bv1);
            float2 r1 = make_float2(acc[mt][nt][2] + bv0, acc[mt][nt][3] + bv1);
            *(float2*)(C + row * ldc + col) = r0;
            *(float2*)(C + (row + 8) * ldc + col) = r1;
        }
    }
}

// ---------------- fused prep: Whh planes + bias + barrier reset ------------------
__global__ void k_prep_all(const float* __restrict__ Whh,
                           const float* __restrict__ bih,
                           const float* __restrict__ bhh) {
    if (blockIdx.x == 0) {
        if (threadIdx.x < TT) g_bar[threadIdx.x] = 0u;
        for (int i = threadIdx.x; i < 4 * HH; i += 256)
            g_bias2[i] = bih[i] + bhh[i];
    }
    int o4 = blockIdx.x * 256 + threadIdx.x;        // uint4 index over 2048*128
    if (o4 >= 2048 * 128) return;
    int o = o4 >> 7, c4 = o4 & 127;
    int blk = o >> 6, z = (o >> 4) & 3, jj = o & 15;
    float4 v = *((const float4*)(Whh + (size_t)(z * HH + blk * 16 + jj) * HH) + c4);
    float av[4] = {v.x, v.y, v.z, v.w};
    uint32_t hi[4], lo[4];
#pragma unroll
    for (int q = 0; q < 4; q++) {
        hi[q] = f2tf32(av[q]);
        lo[q] = f2tf32(av[q] - __uint_as_float(hi[q]));
    }
    *(uint4*)&g_whh_hi[(size_t)o * HH + c4 * 4] = *(uint4*)hi;
    *(uint4*)&g_whh_lo[(size_t)o * HH + c4 * 4] = *(uint4*)lo;
}

// h0 -> tf32 hi/lo planes, parity 0 (read at t=0).
__global__ void k_prep_h0(const float* __restrict__ h0) {
    int i4 = blockIdx.x * 256 + threadIdx.x;        // over 32*512/4
    if (i4 >= BB * HH / 4) return;
    float4 v = ((const float4*)h0)[i4];
    float av[4] = {v.x, v.y, v.z, v.w};
    uint32_t hi[4], lo[4];
#pragma unroll
    for (int q = 0; q < 4; q++) {
        hi[q] = f2tf32(av[q]);
        lo[q] = f2tf32(av[q] - __uint_as_float(hi[q]));
    }
    *(uint4*)&g_hpl[0][0][i4 * 4] = *(uint4*)hi;
    *(uint4*)&g_hpl[0][1][i4 * 4] = *(uint4*)lo;
}

// ---------------- persistent decode: split acc chains; ATOMIC barrier poll -------
// (round-10's relaxed ld.cg poll released the barrier early -> stale h -> 2.5e-2
//  rel_err. Atomic RMW poll is the known-good coherent form; keep it.)
// smem: 2 stages x [Ah 32x68 | Al 32x68 | Bh 64x68 | Bl 64x68] + dmp + csh = 115,200 B
__global__ __launch_bounds__(256) void k_decode(const float* __restrict__ c0)
{
    extern __shared__ uint32_t sm[];
    constexpr int ASZ = 32 * 68, BSZ = 64 * 68;
    constexpr int STG = 2 * ASZ + 2 * BSZ;          // 13056 words
    float* dmp = (float*)(sm + 2 * STG);            // 32*68 floats
    float* csh = dmp + 32 * 68;                     // 512 floats

    const int blk = blockIdx.x, tid = threadIdx.x;
    const int warp = tid >> 5, lane = tid & 31, g = lane >> 2, tg = lane & 3;
    const int jb = blk * 16;

    for (int u = tid; u < 512; u += 256)
        csh[u] = c0[(u >> 4) * HH + jb + (u & 15)];

    const uint32_t* whh_hi = g_whh_hi + (size_t)blk * 64 * HH;
    const uint32_t* whh_lo = g_whh_lo + (size_t)blk * 64 * HH;
    __syncthreads();

    for (int t = 0; t < TT; t++) {
        const uint32_t* hh = g_hpl[t & 1][0];
        const uint32_t* hl = g_hpl[t & 1][1];

        // prefetch this step's gates_x scalars (independent of h)
        float gx[2][4];
#pragma unroll
        for (int rep = 0; rep < 2; rep++) {
            int u = tid + rep * 256;
            size_t gbase = ((size_t)(u >> 4) * TT + t) * (4 * HH) + jb + (u & 15);
            gx[rep][0] = __ldcg(&g_gatesx[gbase]);
            gx[rep][1] = __ldcg(&g_gatesx[gbase + HH]);
            gx[rep][2] = __ldcg(&g_gatesx[gbase + 2 * HH]);
            gx[rep][3] = __ldcg(&g_gatesx[gbase + 3 * HH]);
        }

        uint4 rAh[2], rAl[2], rBh[4], rBl[4];
        auto ldg_dec = [&](int kt) {
#pragma unroll
            for (int i = 0; i < 2; i++) {           // A planes: h written by other SMs -> L2-only
                int idx = i * 256 + tid;
                int row = idx >> 4, c4 = idx & 15;
                rAh[i] = __ldcg((const uint4*)(hh + (size_t)row * HH + kt) + c4);
                rAl[i] = __ldcg((const uint4*)(hl + (size_t)row * HH + kt) + c4);
            }
#pragma unroll
            for (int i = 0; i < 4; i++) {           // B planes: constant, L1-cacheable
                int idx = i * 256 + tid;
                int row = idx >> 4, c4 = idx & 15;
                rBh[i] = *((const uint4*)(whh_hi + (size_t)row * HH + kt) + c4);
                rBl[i] = *((const uint4*)(whh_lo + (size_t)row * HH + kt) + c4);
            }
        };
        auto sts_dec = [&](int s) {
            uint32_t* Ah = sm + s * STG;
            uint32_t* Al = Ah + ASZ;
            uint32_t* Bh = Al + ASZ;
            uint32_t* Bl = Bh + BSZ;
#pragma unroll
            for (int i = 0; i < 2; i++) {
                int idx = i * 256 + tid;
                int row = idx >> 4, c4 = idx & 15;
                *(uint4*)&Ah[row * 68 + c4 * 4] = rAh[i];
                *(uint4*)&Al[row * 68 + c4 * 4] = rAl[i];
            }
#pragma unroll
            for (int i = 0; i < 4; i++) {
                int idx = i * 256 + tid;
                int row = idx >> 4, c4 = idx & 15;
                *(uint4*)&Bh[row * 68 + c4 * 4] = rBh[i];
                *(uint4*)&Bl[row * 68 + c4 * 4] = rBl[i];
            }
        };

        // 4 accumulator chains: [mt][ks-parity] — halves MMA dependency chain length
        float acc[2][2][4];
#pragma unroll
        for (int mt = 0; mt < 2; mt++)
#pragma unroll
            for (int ch = 0; ch < 2; ch++)
#pragma unroll
                for (int q = 0; q < 4; q++) acc[mt][ch][q] = 0.0f;

        ldg_dec(0);
        sts_dec(0);
        __syncthreads();

        for (int ki = 0; ki < 8; ki++) {
            const int cur = ki & 1;
            if (ki + 1 < 8) ldg_dec((ki + 1) * 64);

            const uint32_t* Ah = sm + cur * STG;
            const uint32_t* Al = Ah + ASZ;
            const uint32_t* Bh = Al + ASZ;
            const uint32_t* Bl = Bh + BSZ;
#pragma unroll
            for (int ks = 0; ks < 8; ks++) {
                const int k0 = ks * 8;
                const int ch = ks & 1;
                uint32_t ah[2][4], al2[2][4], bh[2], bl2[2];
#pragma unroll
                for (int mt = 0; mt < 2; mt++) {
                    int rb = mt * 16;
                    ah[mt][0] = Ah[(rb + g) * 68 + k0 + tg];
                    ah[mt][1] = Ah[(rb + g + 8) * 68 + k0 + tg];
                    ah[mt][2] = Ah[(rb + g) * 68 + k0 + tg + 4];
                    ah[mt][3] = Ah[(rb + g + 8) * 68 + k0 + tg + 4];
                    al2[mt][0] = Al[(rb + g) * 68 + k0 + tg];
                    al2[mt][1] = Al[(rb + g + 8) * 68 + k0 + tg];
                    al2[mt][2] = Al[(rb + g) * 68 + k0 + tg + 4];
                    al2[mt][3] = Al[(rb + g + 8) * 68 + k0 + tg + 4];
                }
                int nb = warp * 8 + g;
                bh[0] = Bh[nb * 68 + k0 + tg];
                bh[1] = Bh[nb * 68 + k0 + tg + 4];
                bl2[0] = Bl[nb * 68 + k0 + tg];
                bl2[1] = Bl[nb * 68 + k0 + tg + 4];
#pragma unroll
                for (int mt = 0; mt < 2; mt++) {
                    mma_tf32(acc[mt][ch], ah[mt], bh);
                    mma_tf32(acc[mt][ch], al2[mt], bh);
                    mma_tf32(acc[mt][ch], ah[mt], bl2);
                }
            }

            if (ki + 1 < 8) sts_dec(1 - cur);
            __syncthreads();
        }

        // merge chains + dump C [32 b, 64 n]
#pragma unroll
        for (int mt = 0; mt < 2; mt++) {
            int row = mt * 16 + g, col = warp * 8 + 2 * tg;
            dmp[row * 68 + col]           = acc[mt][0][0] + acc[mt][1][0];
            dmp[row * 68 + col + 1]       = acc[mt][0][1] + acc[mt][1][1];
            dmp[(row + 8) * 68 + col]     = acc[mt][0][2] + acc[mt][1][2];
            dmp[(row + 8) * 68 + col + 1] = acc[mt][0][3] + acc[mt][1][3];
        }
        __syncthreads();

        // LSTM pointwise; write h fp32 + tf32 planes (parity (t+1)&1)
        uint32_t* whi = g_hpl[(t + 1) & 1][0];
        uint32_t* wlo = g_hpl[(t + 1) & 1][1];
#pragma unroll
        for (int rep = 0; rep < 2; rep++) {
            int u = tid + rep * 256;
            int b = u >> 4, jj = u & 15;
            float iv = dmp[b * 68 + jj]      + gx[rep][0];
            float fv = dmp[b * 68 + 16 + jj] + gx[rep][1];
            float gv = dmp[b * 68 + 32 + jj] + gx[rep][2];
            float ov = dmp[b * 68 + 48 + jj] + gx[rep][3];
            float cn = sigf(fv) * csh[u] + sigf(iv) * tanhf(gv);
            float hn = sigf(ov) * tanhf(cn);
            csh[u] = cn;
            __stcg(&g_hhist[((size_t)b * TT + t) * HH + jb + jj], hn);
            uint32_t hi = f2tf32(hn);
            __stcg(&whi[b * HH + jb + jj], hi);
            __stcg(&wlo[b * HH + jb + jj], f2tf32(hn - __uint_as_float(hi)));
        }
        __threadfence();
        __syncthreads();
        if (tid == 0) {
            atomicAdd(&g_bar[t], 1u);
            while (atomicAdd(&g_bar[t], 0u) < NDEC) {}   // atomic RMW poll: coherent
        }
        __syncthreads();
    }
}

// ---------------- post-loop: scores + softmax (parallel over b) ----------
__global__ __launch_bounds__(256) void k_scores(const int* __restrict__ lens)
{
    extern __shared__ uint32_t dynsm[];
    uint32_t* Ah = dynsm;                 // 64*20
    uint32_t* Al = Ah + 64 * 20;
    uint32_t* Bh = Al + 64 * 20;          // 128*20
    uint32_t* Bl = Bh + 128 * 20;
    float* sc = (float*)dynsm;            // 64*132 overlay (phase-separated)

    const int b = blockIdx.x, tid = threadIdx.x;
    const int warp = tid >> 5, lane = tid & 31, g = lane >> 2, tg = lane & 3;
    const int wm = (warp & 1) * 32, wn = (warp >> 1) * 32;

    float acc[2][4][4];
#pragma unroll
    for (int i = 0; i < 2; i++)
#pragma unroll
        for (int j = 0; j < 4; j++)
#pragma unroll
            for (int q = 0; q < 4; q++) acc[i][j][q] = 0.0f;

    for (int kt = 0; kt < HH; kt += 16) {
        {
            int row = tid >> 2, c4 = tid & 3;
            float4 v = *((const float4*)(g_hhist + ((size_t)b * TT + row) * HH + kt) + c4);
            float av[4] = {v.x, v.y, v.z, v.w};
            uint32_t* da = &Ah[row * 20 + c4 * 4];
            uint32_t* dl = &Al[row * 20 + c4 * 4];
#pragma unroll
            for (int q = 0; q < 4; q++) {
                uint32_t h = f2tf32(av[q]);
                da[q] = h;
                dl[q] = f2tf32(av[q] - __uint_as_float(h));
            }
        }
#pragma unroll
        for (int i = 0; i < 2; i++) {
            int idx = i * 256 + tid;
            int row = idx >> 2, c4 = idx & 3;
            float4 v = *((const float4*)(g_proj_enc + ((size_t)b * SS + row) * HH + kt) + c4);
            float bv[4] = {v.x, v.y, v.z, v.w};
            uint32_t* db = &Bh[row * 20 + c4 * 4];
            uint32_t* dl = &Bl[row * 20 + c4 * 4];
#pragma unroll
            for (int q = 0; q < 4; q++) {
                uint32_t h = f2tf32(bv[q]);
                db[q] = h;
                dl[q] = f2tf32(bv[q] - __uint_as_float(h));
            }
        }
        __syncthreads();
#pragma unroll
        for (int ks = 0; ks < 2; ks++) {
            const int k0 = ks * 8;
            uint32_t ah[2][4], al2[2][4], bh[4][2], bl2[4][2];
#pragma unroll
            for (int mt = 0; mt < 2; mt++) {
                int rb = wm + mt * 16;
                ah[mt][0] = Ah[(rb + g) * 20 + k0 + tg];
                ah[mt][1] = Ah[(rb + g + 8) * 20 + k0 + tg];
                ah[mt][2] = Ah[(rb + g) * 20 + k0 + tg + 4];
                ah[mt][3] = Ah[(rb + g + 8) * 20 + k0 + tg + 4];
                al2[mt][0] = Al[(rb + g) * 20 + k0 + tg];
                al2[mt][1] = Al[(rb + g + 8) * 20 + k0 + tg];
                al2[mt][2] = Al[(rb + g) * 20 + k0 + tg + 4];
                al2[mt][3] = Al[(rb + g + 8) * 20 + k0 + tg + 4];
            }
#pragma unroll
            for (int nt = 0; nt < 4; nt++) {
                int nb = wn + nt * 8 + g;
                bh[nt][0] = Bh[nb * 20 + k0 + tg];
                bh[nt][1] = Bh[nb * 20 + k0 + tg + 4];
                bl2[nt][0] = Bl[nb * 20 + k0 + tg];
                bl2[nt][1] = Bl[nb * 20 + k0 + tg + 4];
            }
#pragma unroll
            for (int mt = 0; mt < 2; mt++)
#pragma unroll
                for (int nt = 0; nt < 4; nt++) {
                    mma_tf32(acc[mt][nt], ah[mt], bh[nt]);
                    mma_tf32(acc[mt][nt], al2[mt], bh[nt]);
                    mma_tf32(acc[mt][nt], ah[mt], bl2[nt]);
                }
        }
        __syncthreads();
    }

#pragma unroll
    for (int mt = 0; mt < 2; mt++)
#pragma unroll
        for (int nt = 0; nt < 4; nt++) {
            int row = wm + mt * 16 + g, col = wn + nt * 8 + 2 * tg;
            sc[row * 132 + col] = acc[mt][nt][0];
            sc[row * 132 + col + 1] = acc[mt][nt][1];
            sc[(row + 8) * 132 + col] = acc[mt][nt][2];
            sc[(row + 8) * 132 + col + 1] = acc[mt][nt][3];
        }
    __syncthreads();

    const int len = lens[b];
    for (int i = 0; i < 8; i++) {
        int t = warp * 8 + i;
        float v[4], mx = -3.0e38f;
#pragma unroll
        for (int q = 0; q < 4; q++) {
            int s = lane + q * 32;
            v[q] = (s < len) ? sc[t * 132 + s] : -3.0e38f;
            mx = fmaxf(mx, v[q]);
        }
        for (int off = 16; off > 0; off >>= 1)
            mx = fmaxf(mx, __shfl_xor_sync(0xFFFFFFFFu, mx, off));
        float e[4], sum = 0.0f;
#pragma unroll
        for (int q = 0; q < 4; q++) {
            int s = lane + q * 32;
            e[q] = (s < len) ? expf(v[q] - mx) : 0.0f;
            sum += e[q];
        }
        for (int off = 16; off > 0; off >>= 1)
            sum += __shfl_xor_sync(0xFFFFFFFFu, sum, off);
        float inv = 1.0f / sum;
#pragma unroll
        for (int q = 0; q < 4; q++)
            g_att2[((size_t)b * TT + t) * SS + lane + q * 32] = e[q] * inv;
    }
}

// ---------------- post-loop: HO += att @ proj2 (batched per b) ----------
__global__ __launch_bounds__(256) void k_ctx()
{
    __shared__ float att_sh[TT * SS];
    const int b = blockIdx.y, jt = blockIdx.x, tid = threadIdx.x;

    for (int i = tid; i < TT * SS / 4; i += 256)
        ((float4*)att_sh)[i] = ((const float4*)(g_att2 + (size_t)b * TT * SS))[i];
    __syncthreads();

    const int j = jt * 128 + (tid & 127);
    const int th = tid >> 7;
    float acc[32];
#pragma unroll
    for (int tt = 0; tt < 32; tt++) acc[tt] = 0.0f;

    const float* p2 = g_proj2 + (size_t)b * SS * HH + j;
    const float* ar = att_sh + (th * 32) * SS;
#pragma unroll 4
    for (int s = 0; s < SS; s++) {
        float v = p2[(size_t)s * HH];
#pragma unroll
        for (int tt = 0; tt < 32; tt++)
            acc[tt] += ar[tt * SS + s] * v;
    }
#pragma unroll
    for (int tt = 0; tt < 32; tt++) {
        size_t o = ((size_t)b * TT + th * 32 + tt) * HH + j;
        g_ho[o] += acc[tt];
    }
}

// ---------------- launcher ----------------
extern "C" void kernel_launch(void* const* d_in, const int* in_sizes, int n_in,
                              void* d_out, int out_size)
{
    const int* tok = (const int*)d_in[0];
    const float* enc = (const float*)d_in[1];
    const int* lens = (const int*)d_in[2];
    const float* h0 = (const float*)d_in[3];
    const float* c0 = (const float*)d_in[4];
    const float* emb = (const float*)d_in[5];
    const float* Wih = (const float*)d_in[6];
    const float* Whh = (const float*)d_in[7];
    const float* bih = (const float*)d_in[8];
    const float* bhh = (const float*)d_in[9];
    const float* Wa = (const float*)d_in[10];
    const float* Wcw = (const float*)d_in[11];
    const float* Wcb = (const float*)d_in[12];
    const float* Wow = (const float*)d_in[13];
    const float* Wob = (const float*)d_in[14];
    float* out = (float*)d_out;

    float *p_gatesx, *p_hhist, *p_proj, *p_proj2, *p_ho, *p_bias;
    cudaGetSymbolAddress((void**)&p_gatesx, g_gatesx);
    cudaGetSymbolAddress((void**)&p_hhist, g_hhist);
    cudaGetSymbolAddress((void**)&p_proj, g_proj_enc);
    cudaGetSymbolAddress((void**)&p_proj2, g_proj2);
    cudaGetSymbolAddress((void**)&p_ho, g_ho);
    cudaGetSymbolAddress((void**)&p_bias, g_bias2);

    // smem opt-ins (one per template instantiation!)
    const int NC_DYN = 2 * 2 * (128 * 36) * 4;          // 73,728 B
    const int CP_DYN = 2 * 2 * (2 * 128 * 20) * 4;      // 81,920 B
    cudaFuncSetAttribute(gemm_db<false, true>,  cudaFuncAttributeMaxDynamicSharedMemorySize, NC_DYN);
    cudaFuncSetAttribute(gemm_db<false, false>, cudaFuncAttributeMaxDynamicSharedMemorySize, NC_DYN);
    cudaFuncSetAttribute(gemm_db<true, false>,  cudaFuncAttributeMaxDynamicSharedMemorySize, CP_DYN);

    const int DEC_DYN = (2 * (2 * 32 * 68 + 2 * 64 * 68) + 32 * 68 + 512) * 4;  // 115,200 B
    cudaFuncSetAttribute(k_decode, cudaFuncAttributeMaxDynamicSharedMemorySize, DEC_DYN);
    const int SC_DYN = 64 * 132 * 4;                    // 33,792 B
    cudaFuncSetAttribute(k_scores, cudaFuncAttributeMaxDynamicSharedMemorySize, SC_DYN);

    // Launch order puts k_decode at stream position 4 (ncu profiles launch #4).

    // #1: fused prep (Whh planes + bias + barrier reset)
    k_prep_all<<<(2048 * 128 + 255) / 256, 256>>>(Whh, bih, bhh);
    // #2: h0 planes
    k_prep_h0<<<(BB * HH / 4 + 255) / 256, 256>>>(h0);
    // #3: A1 gates_x[B*T, 4H] = emb[tok] @ W_ih^T + (b_ih + b_hh)
    gemm_db<false, true><<<dim3(4 * HH / 128, BB * TT / 128), 256, NC_DYN>>>(
        emb, EE, tok, Wih, EE, p_gatesx, 4 * HH, p_bias, EE);
    // #4: persistent LSTM recurrence (64 steps) — ncu target
    k_decode<<<NDEC, 256, DEC_DYN>>>(c0);

    // #5: A2 proj_enc = enc @ Wa^T (compensated tf32)
    gemm_db<true, false><<<dim3(HH / 128, BB * SS / 128), 256, CP_DYN>>>(
        enc, ENCC, nullptr, Wa, ENCC, p_proj, HH, nullptr, ENCC);
    // #6: A3 proj2 = enc @ Wc_c^T (Wc_c = Wc_w[:, H:], row stride H+ENC)
    gemm_db<true, false><<<dim3(HH / 128, BB * SS / 128), 256, CP_DYN>>>(
        enc, ENCC, nullptr, Wcw + HH, HH + ENCC, p_proj2, HH, nullptr, ENCC);
    // #7: scores + softmax
    k_scores<<<BB, 256, SC_DYN>>>(lens);
    // #8: HO = Hhist @ Wc_h^T + Wcb (compensated tf32; Wc_h = Wc_w[:, :H])
    gemm_db<true, false><<<dim3(HH / 128, BB * TT / 128), 256, CP_DYN>>>(
        p_hhist, HH, nullptr, Wcw, HH + ENCC, p_ho, HH, Wcb, HH);
    // #9: HO += att @ proj2
    k_ctx<<<dim3(4, BB), 256>>>();
    // #10: D logits = HO @ Wo^T + Wo_b
    gemm_db<false, false><<<dim3(VV / 128, BB * TT / 128), 256, NC_DYN>>>(
        p_ho, HH, nullptr, Wow, HH, out, VV, Wob, HH);
}

// round 13
// speedup vs baseline: 1.2847x; 1.2847x over previous
#include <cuda_runtime.h>
#include <cuda_bf16.h>
#include <cstdint>

#define BB 32
#define TT 64
#define SS 128
#define EE 256
#define HH 512
#define ENCC 512
#define VV 32000
#define NDEC 32   // blocks in persistent decode kernel (one wave, co-resident)

// ---------------- scratch (device globals; no allocation) ----------------
__device__ float g_gatesx[BB * TT * 4 * HH];        // 16 MB [b,t,4H] = emb@Wih^T + bias
__device__ float g_hhist[BB * TT * HH];             // 4 MB  h after step t: [b,t,h]
__device__ float g_proj_enc[BB * SS * HH];          // 8 MB  enc @ Wa^T
__device__ float g_proj2[BB * SS * HH];             // 8 MB  enc @ Wc_c^T
__device__ float g_att2[BB * TT * SS];              // 1 MB  att per (b,t)
__device__ float g_ho[BB * TT * HH];                // 4 MB
__device__ float g_bias2[4 * HH];                   // b_ih + b_hh
__device__ unsigned g_bar[TT];                      // decode grid barrier counters
// MMA-fragment-order packed operands (precomputed; mainloop has NO smem staging):
// B' per block: [k8(64)][n(64)][tg(4)][q(4)] q=(hi,k0+tg)(hi,+4)(lo,)(lo,+4); 65536 words
__device__ uint32_t g_whh_pk[NDEC * 65536];         // 8 MB
// A' planes: [(k8*2+mt)(128)][g(8)][tg(4)][q(4)] q=colhalf*2+rowhalf; 16384 words/plane
__device__ uint32_t g_hplA[2][2][16384];            // [parity][hi/lo]

// ---------------- helpers ----------------
__device__ __forceinline__ uint32_t f2tf32(float x) {
    uint32_t r;
    asm("cvt.rna.tf32.f32 %0, %1;" : "=r"(r) : "f"(x));
    return r;
}

__device__ __forceinline__ void mma_tf32(float* d, const uint32_t* a, const uint32_t* b) {
    asm("mma.sync.aligned.m16n8k8.row.col.f32.tf32.tf32.f32 "
        "{%0,%1,%2,%3}, {%4,%5,%6,%7}, {%8,%9}, {%0,%1,%2,%3};"
        : "+f"(d[0]), "+f"(d[1]), "+f"(d[2]), "+f"(d[3])
        : "r"(a[0]), "r"(a[1]), "r"(a[2]), "r"(a[3]), "r"(b[0]), "r"(b[1]));
}

__device__ __forceinline__ float sigf(float x) { return 1.0f / (1.0f + expf(-x)); }

// ------- double-buffered tf32 GEMM: C[M,N] = A[M,K] @ B[N,K]^T (+bias) -----------
template <bool COMP, bool GATHER>
__global__ __launch_bounds__(256) void gemm_db(
    const float* __restrict__ A, int lda, const int* __restrict__ gidx,
    const float* __restrict__ B, int ldb,
    float* __restrict__ C, int ldc,
    const float* __restrict__ bias0, int K)
{
    constexpr int KT = COMP ? 16 : 32;
    constexpr int PAD = COMP ? 20 : 36;
    constexpr int PLANE = 128 * PAD;
    constexpr int NPL = COMP ? 2 : 1;
    constexpr int STG = NPL * PLANE;
    constexpr int C4 = KT / 4;
    constexpr int NL = (128 * C4) / 256;

    extern __shared__ uint32_t sm[];
    uint32_t* As = sm;
    uint32_t* Bs = sm + 2 * STG;

    const int tid = threadIdx.x;
    const int warp = tid >> 5, lane = tid & 31;
    const int g = lane >> 2, tg = lane & 3;
    const int wm = (warp & 1) * 64, wn = (warp >> 1) * 32;
    const long m0 = (long)blockIdx.y * 128, n0 = (long)blockIdx.x * 128;

    float acc[4][4][4];
#pragma unroll
    for (int i = 0; i < 4; i++)
#pragma unroll
        for (int j = 0; j < 4; j++)
#pragma unroll
            for (int q = 0; q < 4; q++) acc[i][j][q] = 0.0f;

    const int nk = K / KT;
    float4 ra[NL], rb[NL];

    auto ldg_tile = [&](int kt) {
#pragma unroll
        for (int i = 0; i < NL; i++) {
            int idx = i * 256 + tid;
            int row = idx / C4, c4 = idx % C4;
            const float* ap = GATHER ? (A + (size_t)gidx[m0 + row] * lda)
                                     : (A + (size_t)(m0 + row) * lda);
            ra[i] = *(const float4*)(ap + kt + c4 * 4);
            rb[i] = *(const float4*)(B + (size_t)(n0 + row) * ldb + kt + c4 * 4);
        }
    };
    auto sts_tile = [&](int stg) {
        uint32_t* as = As + stg * STG;
        uint32_t* bs = Bs + stg * STG;
#pragma unroll
        for (int i = 0; i < NL; i++) {
            int idx = i * 256 + tid;
            int row = idx / C4, c4 = idx % C4;
            uint32_t* da = &as[row * PAD + c4 * 4];
            uint32_t* db = &bs[row * PAD + c4 * 4];
            float av[4] = {ra[i].x, ra[i].y, ra[i].z, ra[i].w};
            float bv[4] = {rb[i].x, rb[i].y, rb[i].z, rb[i].w};
#pragma unroll
            for (int q = 0; q < 4; q++) {
                uint32_t ah = f2tf32(av[q]);
                uint32_t bh = f2tf32(bv[q]);
                da[q] = ah;
                db[q] = bh;
                if (COMP) {
                    da[q + PLANE] = f2tf32(av[q] - __uint_as_float(ah));
                    db[q + PLANE] = f2tf32(bv[q] - __uint_as_float(bh));
                }
            }
        }
    };

    ldg_tile(0);
    sts_tile(0);
    __syncthreads();

    for (int ki = 0; ki < nk; ki++) {
        const int cur = ki & 1;
        if (ki + 1 < nk) ldg_tile((ki + 1) * KT);

        const uint32_t* Ac = As + cur * STG;
        const uint32_t* Bc = Bs + cur * STG;
#pragma unroll
        for (int ks = 0; ks < KT / 8; ks++) {
            const int k0 = ks * 8;
            uint32_t ah[4][4], bh[4][2];
#pragma unroll
            for (int mt = 0; mt < 4; mt++) {
                int rb2 = wm + mt * 16;
                ah[mt][0] = Ac[(rb2 + g) * PAD + k0 + tg];
                ah[mt][1] = Ac[(rb2 + g + 8) * PAD + k0 + tg];
                ah[mt][2] = Ac[(rb2 + g) * PAD + k0 + tg + 4];
                ah[mt][3] = Ac[(rb2 + g + 8) * PAD + k0 + tg + 4];
            }
#pragma unroll
            for (int nt = 0; nt < 4; nt++) {
                int nb = wn + nt * 8 + g;
                bh[nt][0] = Bc[nb * PAD + k0 + tg];
                bh[nt][1] = Bc[nb * PAD + k0 + tg + 4];
            }
            if (COMP) {
                uint32_t al[4][4], bl[4][2];
#pragma unroll
                for (int mt = 0; mt < 4; mt++) {
                    int rb2 = wm + mt * 16;
                    al[mt][0] = Ac[PLANE + (rb2 + g) * PAD + k0 + tg];
                    al[mt][1] = Ac[PLANE + (rb2 + g + 8) * PAD + k0 + tg];
                    al[mt][2] = Ac[PLANE + (rb2 + g) * PAD + k0 + tg + 4];
                    al[mt][3] = Ac[PLANE + (rb2 + g + 8) * PAD + k0 + tg + 4];
                }
#pragma unroll
                for (int nt = 0; nt < 4; nt++) {
                    int nb = wn + nt * 8 + g;
                    bl[nt][0] = Bc[PLANE + nb * PAD + k0 + tg];
                    bl[nt][1] = Bc[PLANE + nb * PAD + k0 + tg + 4];
                }
#pragma unroll
                for (int mt = 0; mt < 4; mt++)
#pragma unroll
                    for (int nt = 0; nt < 4; nt++) {
                        mma_tf32(acc[mt][nt], ah[mt], bh[nt]);
                        mma_tf32(acc[mt][nt], al[mt], bh[nt]);
                        mma_tf32(acc[mt][nt], ah[mt], bl[nt]);
                    }
            } else {
#pragma unroll
                for (int mt = 0; mt < 4; mt++)
#pragma unroll
                    for (int nt = 0; nt < 4; nt++)
                        mma_tf32(acc[mt][nt], ah[mt], bh[nt]);
            }
        }

        if (ki + 1 < nk) sts_tile(1 - cur);
        __syncthreads();
    }

#pragma unroll
    for (int nt = 0; nt < 4; nt++) {
        long col = n0 + wn + nt * 8 + 2 * tg;
        float bv0 = bias0 ? bias0[col] : 0.0f;
        float bv1 = bias0 ? bias0[col + 1] : 0.0f;
#pragma unroll
        for (int mt = 0; mt < 4; mt++) {
            long row = m0 + wm + mt * 16 + g;
            float2 r0 = make_float2(acc[mt][nt][0] + bv0, acc[mt][nt][1] + bv1);
            float2 r1 = make_float2(acc[mt][nt][2] + bv0, acc[mt][nt][3] + bv1);
            *(float2*)(C + row * ldc + col) = r0;
            *(float2*)(C + (row + 8) * ldc + col) = r1;
        }
    }
}

// ---------------- fused prep: packed B' + bias + barrier reset -------------------
// Whh row r = z*H + jg, col k  ->  block jg/16, n = z*16 + jg%16,
// word(in blk region) = k8*1024 + n*16 + tg*4 + (plane*2 + colhalf).
__global__ void k_prep_all(const float* __restrict__ Whh,
                           const float* __restrict__ bih,
                           const float* __restrict__ bhh) {
    if (blockIdx.x == 0) {
        if (threadIdx.x < TT) g_bar[threadIdx.x] = 0u;
        for (int i = threadIdx.x; i < 4 * HH; i += 256)
            g_bias2[i] = bih[i] + bhh[i];
    }
    int o4 = blockIdx.x * 256 + threadIdx.x;        // over 2048 rows * 128 float4
    if (o4 >= 2048 * 128) return;
    int r = o4 >> 7, c4 = o4 & 127;
    int z = r >> 9, jg = r & 511;
    int blk = jg >> 4;
    int n = z * 16 + (jg & 15);
    int k = c4 * 4;
    int k8 = k >> 3, colhalf = (k >> 2) & 1;
    float4 v = *((const float4*)(Whh + (size_t)r * HH) + c4);
    float av[4] = {v.x, v.y, v.z, v.w};
    uint32_t* dst = g_whh_pk + (size_t)blk * 65536 + k8 * 1024 + n * 16 + colhalf;
#pragma unroll
    for (int tg = 0; tg < 4; tg++) {
        uint32_t hi = f2tf32(av[tg]);
        dst[tg * 4]     = hi;                                    // q = 0*2 + colhalf
        dst[tg * 4 + 2] = f2tf32(av[tg] - __uint_as_float(hi));  // q = 1*2 + colhalf
    }
}

// h0 -> A' fragment planes, parity 0.
__global__ void k_prep_h0(const float* __restrict__ h0) {
    int idx = blockIdx.x * 256 + threadIdx.x;       // over 32*512 elements
    if (idx >= BB * HH) return;
    int b = idx >> 9, j = idx & 511;
    float v = h0[b * HH + j];
    int word = (((j >> 3) * 2 + (b >> 4)) * 128) + (b & 7) * 16 + (j & 3) * 4
             + ((j >> 2) & 1) * 2 + ((b >> 3) & 1);
    uint32_t hi = f2tf32(v);
    g_hplA[0][0][word] = hi;
    g_hplA[0][1][word] = f2tf32(v - __uint_as_float(hi));
}

// ---------------- persistent decode v4: fragment LDG, k-split warps, no smem ops -
// Warp w owns k in [w*64, w*64+64), all 64 n, all 32 b. Fragments loaded straight
// from L2 (A' via ldcg — written by peer SMs each step; B' constant, L1 ok).
// Partial C reduced across warps via padded smem (stride 72), fused with LSTM.
// dyn smem: dmp 8*2304 + csh 512 floats = 75,776 B (needs opt-in).
__global__ __launch_bounds__(256) void k_decode(const float* __restrict__ c0)
{
    extern __shared__ float dynf[];
    float* dmp = dynf;                  // [w][m(32) stride 72][n(64)]
    float* csh = dmp + 8 * 2304;        // 512 floats

    const int blk = blockIdx.x, tid = threadIdx.x;
    const int warp = tid >> 5, lane = tid & 31, g = lane >> 2, tg = lane & 3;
    const int jb = blk * 16;
    const int k8b = warp * 8;           // this warp's k8 range: k8b..k8b+7

    for (int u = tid; u < 512; u += 256)
        csh[u] = c0[(u >> 4) * HH + jb + (u & 15)];

    const uint4* Bp = (const uint4*)(g_whh_pk + (size_t)blk * 65536);
    __syncthreads();

    for (int t = 0; t < TT; t++) {
        const uint4* Ahc = (const uint4*)g_hplA[t & 1][0];
        const uint4* Alc = (const uint4*)g_hplA[t & 1][1];

        // prefetch this step's gates_x scalars (independent of h)
        float gx[2][4];
#pragma unroll
        for (int rep = 0; rep < 2; rep++) {
            int u = tid + rep * 256;
            size_t gbase = ((size_t)(u >> 4) * TT + t) * (4 * HH) + jb + (u & 15);
            gx[rep][0] = __ldcg(&g_gatesx[gbase]);
            gx[rep][1] = __ldcg(&g_gatesx[gbase + HH]);
            gx[rep][2] = __ldcg(&g_gatesx[gbase + 2 * HH]);
            gx[rep][3] = __ldcg(&g_gatesx[gbase + 3 * HH]);
        }

        float acc[2][8][4];
#pragma unroll
        for (int mt = 0; mt < 2; mt++)
#pragma unroll
            for (int nt = 0; nt < 8; nt++)
#pragma unroll
                for (int q = 0; q < 4; q++) acc[mt][nt][q] = 0.0f;

        uint4 aB[2][2][2], bB[2][8];    // [parity][...]
        auto ldA = [&](int k8, int p) {
#pragma unroll
            for (int mt = 0; mt < 2; mt++) {
                aB[p][mt][0] = __ldcg(Ahc + (k8 * 2 + mt) * 32 + lane);
                aB[p][mt][1] = __ldcg(Alc + (k8 * 2 + mt) * 32 + lane);
            }
        };
        auto ldB = [&](int k8, int p) {
#pragma unroll
            for (int nt = 0; nt < 8; nt++)
                bB[p][nt] = Bp[k8 * 256 + nt * 32 + lane];
        };

        ldA(k8b, 0);
        ldB(k8b, 0);
#pragma unroll
        for (int ks = 0; ks < 8; ks++) {
            const int cur = ks & 1;
            if (ks + 1 < 8) { ldA(k8b + ks + 1, 1 - cur); ldB(k8b + ks + 1, 1 - cur); }
#pragma unroll
            for (int mt = 0; mt < 2; mt++) {
                uint32_t ah[4] = {aB[cur][mt][0].x, aB[cur][mt][0].y,
                                  aB[cur][mt][0].z, aB[cur][mt][0].w};
                uint32_t al[4] = {aB[cur][mt][1].x, aB[cur][mt][1].y,
                                  aB[cur][mt][1].z, aB[cur][mt][1].w};
#pragma unroll
                for (int nt = 0; nt < 8; nt++) {
                    uint32_t bh[2] = {bB[cur][nt].x, bB[cur][nt].y};
                    uint32_t bl[2] = {bB[cur][nt].z, bB[cur][nt].w};
                    mma_tf32(acc[mt][nt], ah, bh);
                    mma_tf32(acc[mt][nt], al, bh);
                    mma_tf32(acc[mt][nt], ah, bl);
                }
            }
        }

        // dump partial C [32 b, 64 n] for this warp's k-slice (stride 72: conflict-free)
#pragma unroll
        for (int mt = 0; mt < 2; mt++)
#pragma unroll
            for (int nt = 0; nt < 8; nt++) {
                int row = mt * 16 + g, col = nt * 8 + tg * 2;
                *(float2*)&dmp[warp * 2304 + row * 72 + col] =
                    make_float2(acc[mt][nt][0], acc[mt][nt][1]);
                *(float2*)&dmp[warp * 2304 + (row + 8) * 72 + col] =
                    make_float2(acc[mt][nt][2], acc[mt][nt][3]);
            }
        __syncthreads();

        // reduce 8 warps + LSTM pointwise; write h fp32 + A' fragment planes
        uint32_t* whi = g_hplA[(t + 1) & 1][0];
        uint32_t* wlo = g_hplA[(t + 1) & 1][1];
#pragma unroll
        for (int rep = 0; rep < 2; rep++) {
            int u = tid + rep * 256;
            int b = u >> 4, jj = u & 15;
            float gate[4];
#pragma unroll
            for (int z = 0; z < 4; z++) {
                float s = 0.0f;
#pragma unroll
                for (int w = 0; w < 8; w++)
                    s += dmp[w * 2304 + b * 72 + z * 16 + jj];
                gate[z] = s + gx[rep][z];
            }
            float cn = sigf(gate[1]) * csh[u] + sigf(gate[0]) * tanhf(gate[2]);
            float hn = sigf(gate[3]) * tanhf(cn);
            csh[u] = cn;
            int j = jb + jj;
            __stcg(&g_hhist[((size_t)b * TT + t) * HH + j], hn);
            int word = (((j >> 3) * 2 + (b >> 4)) * 128) + (b & 7) * 16 + (j & 3) * 4
                     + ((j >> 2) & 1) * 2 + ((b >> 3) & 1);
            uint32_t hi = f2tf32(hn);
            __stcg(&whi[word], hi);
            __stcg(&wlo[word], f2tf32(hn - __uint_as_float(hi)));
        }
        __threadfence();
        __syncthreads();
        if (tid == 0) {
            atomicAdd(&g_bar[t], 1u);
            while (atomicAdd(&g_bar[t], 0u) < NDEC) {}   // atomic RMW poll: coherent
        }
        __syncthreads();
    }
}

// ---------------- post-loop: scores + softmax (parallel over b) ----------
__global__ __launch_bounds__(256) void k_scores(const int* __restrict__ lens)
{
    extern __shared__ uint32_t dynsm[];
    uint32_t* Ah = dynsm;                 // 64*20
    uint32_t* Al = Ah + 64 * 20;
    uint32_t* Bh = Al + 64 * 20;          // 128*20
    uint32_t* Bl = Bh + 128 * 20;
    float* sc = (float*)dynsm;            // 64*132 overlay (phase-separated)

    const int b = blockIdx.x, tid = threadIdx.x;
    const int warp = tid >> 5, lane = tid & 31, g = lane >> 2, tg = lane & 3;
    const int wm = (warp & 1) * 32, wn = (warp >> 1) * 32;

    float acc[2][4][4];
#pragma unroll
    for (int i = 0; i < 2; i++)
#pragma unroll
        for (int j = 0; j < 4; j++)
#pragma unroll
            for (int q = 0; q < 4; q++) acc[i][j][q] = 0.0f;

    for (int kt = 0; kt < HH; kt += 16) {
        {
            int row = tid >> 2, c4 = tid & 3;
            float4 v = *((const float4*)(g_hhist + ((size_t)b * TT + row) * HH + kt) + c4);
            float av[4] = {v.x, v.y, v.z, v.w};
            uint32_t* da = &Ah[row * 20 + c4 * 4];
            uint32_t* dl = &Al[row * 20 + c4 * 4];
#pragma unroll
            for (int q = 0; q < 4; q++) {
                uint32_t h = f2tf32(av[q]);
                da[q] = h;
                dl[q] = f2tf32(av[q] - __uint_as_float(h));
            }
        }
#pragma unroll
        for (int i = 0; i < 2; i++) {
            int idx = i * 256 + tid;
            int row = idx >> 2, c4 = idx & 3;
            float4 v = *((const float4*)(g_proj_enc + ((size_t)b * SS + row) * HH + kt) + c4);
            float bv[4] = {v.x, v.y, v.z, v.w};
            uint32_t* db = &Bh[row * 20 + c4 * 4];
            uint32_t* dl = &Bl[row * 20 + c4 * 4];
#pragma unroll
            for (int q = 0; q < 4; q++) {
                uint32_t h = f2tf32(bv[q]);
                db[q] = h;
                dl[q] = f2tf32(bv[q] - __uint_as_float(h));
            }
        }
        __syncthreads();
#pragma unroll
        for (int ks = 0; ks < 2; ks++) {
            const int k0 = ks * 8;
            uint32_t ah[2][4], al2[2][4], bh[4][2], bl2[4][2];
#pragma unroll
            for (int mt = 0; mt < 2; mt++) {
                int rb = wm + mt * 16;
                ah[mt][0] = Ah[(rb + g) * 20 + k0 + tg];
                ah[mt][1] = Ah[(rb + g + 8) * 20 + k0 + tg];
                ah[mt][2] = Ah[(rb + g) * 20 + k0 + tg + 4];
                ah[mt][3] = Ah[(rb + g + 8) * 20 + k0 + tg + 4];
                al2[mt][0] = Al[(rb + g) * 20 + k0 + tg];
                al2[mt][1] = Al[(rb + g + 8) * 20 + k0 + tg];
                al2[mt][2] = Al[(rb + g) * 20 + k0 + tg + 4];
                al2[mt][3] = Al[(rb + g + 8) * 20 + k0 + tg + 4];
            }
#pragma unroll
            for (int nt = 0; nt < 4; nt++) {
                int nb = wn + nt * 8 + g;
                bh[nt][0] = Bh[nb * 20 + k0 + tg];
                bh[nt][1] = Bh[nb * 20 + k0 + tg + 4];
                bl2[nt][0] = Bl[nb * 20 + k0 + tg];
                bl2[nt][1] = Bl[nb * 20 + k0 + tg + 4];
            }
#pragma unroll
            for (int mt = 0; mt < 2; mt++)
#pragma unroll
                for (int nt = 0; nt < 4; nt++) {
                    mma_tf32(acc[mt][nt], ah[mt], bh[nt]);
                    mma_tf32(acc[mt][nt], al2[mt], bh[nt]);
                    mma_tf32(acc[mt][nt], ah[mt], bl2[nt]);
                }
        }
        __syncthreads();
    }

#pragma unroll
    for (int mt = 0; mt < 2; mt++)
#pragma unroll
        for (int nt = 0; nt < 4; nt++) {
            int row = wm + mt * 16 + g, col = wn + nt * 8 + 2 * tg;
            sc[row * 132 + col] = acc[mt][nt][0];
            sc[row * 132 + col + 1] = acc[mt][nt][1];
            sc[(row + 8) * 132 + col] = acc[mt][nt][2];
            sc[(row + 8) * 132 + col + 1] = acc[mt][nt][3];
        }
    __syncthreads();

    const int len = lens[b];
    for (int i = 0; i < 8; i++) {
        int t = warp * 8 + i;
        float v[4], mx = -3.0e38f;
#pragma unroll
        for (int q = 0; q < 4; q++) {
            int s = lane + q * 32;
            v[q] = (s < len) ? sc[t * 132 + s] : -3.0e38f;
            mx = fmaxf(mx, v[q]);
        }
        for (int off = 16; off > 0; off >>= 1)
            mx = fmaxf(mx, __shfl_xor_sync(0xFFFFFFFFu, mx, off));
        float e[4], sum = 0.0f;
#pragma unroll
        for (int q = 0; q < 4; q++) {
            int s = lane + q * 32;
            e[q] = (s < len) ? expf(v[q] - mx) : 0.0f;
            sum += e[q];
        }
        for (int off = 16; off > 0; off >>= 1)
            sum += __shfl_xor_sync(0xFFFFFFFFu, sum, off);
        float inv = 1.0f / sum;
#pragma unroll
        for (int q = 0; q < 4; q++)
            g_att2[((size_t)b * TT + t) * SS + lane + q * 32] = e[q] * inv;
    }
}

// ---------------- post-loop: HO += att @ proj2 (batched per b) ----------
__global__ __launch_bounds__(256) void k_ctx()
{
    __shared__ float att_sh[TT * SS];
    const int b = blockIdx.y, jt = blockIdx.x, tid = threadIdx.x;

    for (int i = tid; i < TT * SS / 4; i += 256)
        ((float4*)att_sh)[i] = ((const float4*)(g_att2 + (size_t)b * TT * SS))[i];
    __syncthreads();

    const int j = jt * 128 + (tid & 127);
    const int th = tid >> 7;
    float acc[32];
#pragma unroll
    for (int tt = 0; tt < 32; tt++) acc[tt] = 0.0f;

    const float* p2 = g_proj2 + (size_t)b * SS * HH + j;
    const float* ar = att_sh + (th * 32) * SS;
#pragma unroll 4
    for (int s = 0; s < SS; s++) {
        float v = p2[(size_t)s * HH];
#pragma unroll
        for (int tt = 0; tt < 32; tt++)
            acc[tt] += ar[tt * SS + s] * v;
    }
#pragma unroll
    for (int tt = 0; tt < 32; tt++) {
        size_t o = ((size_t)b * TT + th * 32 + tt) * HH + j;
        g_ho[o] += acc[tt];
    }
}

// ---------------- launcher ----------------
extern "C" void kernel_launch(void* const* d_in, const int* in_sizes, int n_in,
                              void* d_out, int out_size)
{
    const int* tok = (const int*)d_in[0];
    const float* enc = (const float*)d_in[1];
    const int* lens = (const int*)d_in[2];
    const float* h0 = (const float*)d_in[3];
    const float* c0 = (const float*)d_in[4];
    const float* emb = (const float*)d_in[5];
    const float* Wih = (const float*)d_in[6];
    const float* Whh = (const float*)d_in[7];
    const float* bih = (const float*)d_in[8];
    const float* bhh = (const float*)d_in[9];
    const float* Wa = (const float*)d_in[10];
    const float* Wcw = (const float*)d_in[11];
    const float* Wcb = (const float*)d_in[12];
    const float* Wow = (const float*)d_in[13];
    const float* Wob = (const float*)d_in[14];
    float* out = (float*)d_out;

    float *p_gatesx, *p_hhist, *p_proj, *p_proj2, *p_ho, *p_bias;
    cudaGetSymbolAddress((void**)&p_gatesx, g_gatesx);
    cudaGetSymbolAddress((void**)&p_hhist, g_hhist);
    cudaGetSymbolAddress((void**)&p_proj, g_proj_enc);
    cudaGetSymbolAddress((void**)&p_proj2, g_proj2);
    cudaGetSymbolAddress((void**)&p_ho, g_ho);
    cudaGetSymbolAddress((void**)&p_bias, g_bias2);

    // smem opt-ins (one per template instantiation!)
    const int NC_DYN = 2 * 2 * (128 * 36) * 4;          // 73,728 B
    const int CP_DYN = 2 * 2 * (2 * 128 * 20) * 4;      // 81,920 B
    cudaFuncSetAttribute(gemm_db<false, true>,  cudaFuncAttributeMaxDynamicSharedMemorySize, NC_DYN);
    cudaFuncSetAttribute(gemm_db<false, false>, cudaFuncAttributeMaxDynamicSharedMemorySize, NC_DYN);
    cudaFuncSetAttribute(gemm_db<true, false>,  cudaFuncAttributeMaxDynamicSharedMemorySize, CP_DYN);

    const int DEC_DYN = (8 * 2304 + 512) * 4;           // 75,776 B
    cudaFuncSetAttribute(k_decode, cudaFuncAttributeMaxDynamicSharedMemorySize, DEC_DYN);
    const int SC_DYN = 64 * 132 * 4;                    // 33,792 B
    cudaFuncSetAttribute(k_scores, cudaFuncAttributeMaxDynamicSharedMemorySize, SC_DYN);

    // Launch order puts k_decode at stream position 4 (ncu profiles launch #4).

    // #1: fused prep (packed B' + bias + barrier reset)
    k_prep_all<<<(2048 * 128 + 255) / 256, 256>>>(Whh, bih, bhh);
    // #2: h0 fragment planes
    k_prep_h0<<<(BB * HH + 255) / 256, 256>>>(h0);
    // #3: A1 gates_x[B*T, 4H] = emb[tok] @ W_ih^T + (b_ih + b_hh)
    gemm_db<false, true><<<dim3(4 * HH / 128, BB * TT / 128), 256, NC_DYN>>>(
        emb, EE, tok, Wih, EE, p_gatesx, 4 * HH, p_bias, EE);
    // #4: persistent LSTM recurrence (64 steps) — ncu target
    k_decode<<<NDEC, 256, DEC_DYN>>>(c0);

    // #5: A2 proj_enc = enc @ Wa^T (compensated tf32)
    gemm_db<true, false><<<dim3(HH / 128, BB * SS / 128), 256, CP_DYN>>>(
        enc, ENCC, nullptr, Wa, ENCC, p_proj, HH, nullptr, ENCC);
    // #6: A3 proj2 = enc @ Wc_c^T (Wc_c = Wc_w[:, H:], row stride H+ENC)
    gemm_db<true, false><<<dim3(HH / 128, BB * SS / 128), 256, CP_DYN>>>(
        enc, ENCC, nullptr, Wcw + HH, HH + ENCC, p_proj2, HH, nullptr, ENCC);
    // #7: scores + softmax
    k_scores<<<BB, 256, SC_DYN>>>(lens);
    // #8: HO = Hhist @ Wc_h^T + Wcb (compensated tf32; Wc_h = Wc_w[:, :H])
    gemm_db<true, false><<<dim3(HH / 128, BB * TT / 128), 256, CP_DYN>>>(
        p_hhist, HH, nullptr, Wcw, HH + ENCC, p_ho, HH, Wcb, HH);
    // #9: HO += att @ proj2
    k_ctx<<<dim3(4, BB), 256>>>();
    // #10: D logits = HO @ Wo^T + Wo_b
    gemm_db<false, false><<<dim3(VV / 128, BB * TT / 128), 256, NC_DYN>>>(
        p_ho, HH, nullptr, Wow, HH, out, VV, Wob, HH);
}